// round 2
// baseline (speedup 1.0000x reference)
#include <cuda_runtime.h>
#include <cmath>
#include <complex>
#include <vector>
#include <algorithm>

// ---------------------------------------------------------------------------
// Host-side exact e3nn real-basis Wigner 3j (mirrors reference_code line by line)
// ---------------------------------------------------------------------------
namespace cgh {
typedef std::complex<double> cd;

static double fct(int n) { double r = 1.0; for (int i = 2; i <= n; ++i) r *= (double)i; return r; }

static double su2_cg_coeff(int j1, int m1, int j2, int m2, int j3, int m3) {
    if (m3 != m1 + m2) return 0.0;
    int vmin = std::max(std::max(-j1 + j2 + m3, -j1 + m1), 0);
    int vmax = std::min(std::min(j2 + j3 + m1, j3 - j1 + j2), j3 + m3);
    double C = std::sqrt((2.0 * j3 + 1.0) * fct(j3 + j1 - j2) * fct(j3 - j1 + j2) * fct(j1 + j2 - j3)
                         * fct(j3 + m3) * fct(j3 - m3)
                         / (fct(j1 + j2 + j3 + 1) * fct(j1 - m1) * fct(j1 + m1) * fct(j2 - m2) * fct(j2 + m2)));
    double S = 0.0;
    for (int v = vmin; v <= vmax; ++v) {
        double sgn = ((v + j2 + m2) & 1) ? -1.0 : 1.0;
        S += sgn * fct(j2 + j3 + m1 - v) * fct(j1 - m1 + v)
             / (fct(v) * fct(j3 - j1 + j2 - v) * fct(j3 + m3 - v) * fct(v + j1 - j2 - m3));
    }
    return C * S;
}

static void su2_cg(int j1, int j2, int j3, double* mat) {
    int d1 = 2 * j1 + 1, d2 = 2 * j2 + 1, d3 = 2 * j3 + 1;
    for (int i = 0; i < d1 * d2 * d3; ++i) mat[i] = 0.0;
    if (std::abs(j1 - j2) <= j3 && j3 <= j1 + j2) {
        for (int m1 = -j1; m1 <= j1; ++m1)
            for (int m2 = -j2; m2 <= j2; ++m2)
                if (std::abs(m1 + m2) <= j3)
                    mat[((j1 + m1) * d2 + (j2 + m2)) * d3 + (j3 + m1 + m2)] =
                        su2_cg_coeff(j1, m1, j2, m2, j3, m1 + m2);
    }
    double s = 1.0 / std::sqrt(2.0 * j3 + 1.0);
    for (int i = 0; i < d1 * d2 * d3; ++i) mat[i] *= s;
}

static void basis_r2c(int l, cd* q) {
    int d = 2 * l + 1;
    for (int i = 0; i < d * d; ++i) q[i] = cd(0, 0);
    const double inv = 1.0 / std::sqrt(2.0);
    for (int m = -l; m < 0; ++m) {
        q[(l + m) * d + (l - m)] = cd(inv, 0);      // q[l+m, l+|m|]
        q[(l + m) * d + (l + m)] = cd(0, -inv);     // q[l+m, l-|m|]
    }
    q[l * d + l] = cd(1, 0);
    for (int m = 1; m <= l; ++m) {
        double sgn = (m & 1) ? -1.0 : 1.0;
        q[(l + m) * d + (l + m)] = cd(sgn * inv, 0);
        q[(l + m) * d + (l - m)] = cd(0, sgn * inv);
    }
    cd ph(1, 0), mi(0, -1);
    for (int t = 0; t < l; ++t) ph *= mi;           // (-i)^l phase
    for (int i = 0; i < d * d; ++i) q[i] *= ph;
}

static void wigner3j(int l1, int l2, int l3, double* out) {
    int d1 = 2 * l1 + 1, d2 = 2 * l2 + 1, d3 = 2 * l3 + 1;
    std::vector<cd> Q1(d1 * d1), Q2(d2 * d2), Q3(d3 * d3);
    basis_r2c(l1, Q1.data()); basis_r2c(l2, Q2.data()); basis_r2c(l3, Q3.data());
    std::vector<double> C(d1 * d2 * d3);
    su2_cg(l1, l2, l3, C.data());
    double nrm = 0.0;
    for (int j = 0; j < d1; ++j)
        for (int ll = 0; ll < d2; ++ll)
            for (int m = 0; m < d3; ++m) {
                cd s(0, 0);
                for (int i = 0; i < d1; ++i)
                    for (int k = 0; k < d2; ++k)
                        for (int n = 0; n < d3; ++n)
                            s += Q1[i * d1 + j] * Q2[k * d2 + ll] * std::conj(Q3[n * d3 + m])
                                 * C[(i * d2 + k) * d3 + n];
                out[(j * d2 + ll) * d3 + m] = s.real();
                nrm += s.real() * s.real();
            }
    nrm = std::sqrt(nrm);
    for (int i = 0; i < d1 * d2 * d3; ++i) out[i] /= nrm;
}
} // namespace cgh

// ---------------------------------------------------------------------------
// Coefficients passed by value as kernel parameter (graph-capture safe).
// Structural sparsity of real-basis CG: delta (0x1), delta (1x0), delta (1x1->0),
// Levi-Civita (1x1->1), 11 monomial couplings (1x1->2).
// ---------------------------------------------------------------------------
struct Consts {
    float c000;
    float c2[3];      // 0e x 1o -> 1o : diag
    float c101[3];    // 1o x 0e -> 1o : diag
    float c330[3];    // 1o x 1o -> 0e : diag
    float c4[6];      // 1o x 1o -> 1e : [120,210, 021,201, 012,102]
    float c5[11];     // 1o x 1o -> 2e : [020,200, 011,101, 002,112,222, 123,213, 004,224]
};

static Consts build_consts() {
    Consts K;
    const double s3 = std::sqrt(3.0), s5 = std::sqrt(5.0);
    double w000[1];  cgh::wigner3j(0, 0, 0, w000);
    K.c000 = (float)(w000[0]);
    double w011[9];  cgh::wigner3j(0, 1, 1, w011);     // [j*3+k]
    for (int k = 0; k < 3; ++k) K.c2[k] = (float)(w011[k * 3 + k] * s3);
    double w101[9];  cgh::wigner3j(1, 0, 1, w101);     // [i*3+k]
    for (int k = 0; k < 3; ++k) K.c101[k] = (float)(w101[k * 3 + k] * s3);
    double w110[9];  cgh::wigner3j(1, 1, 0, w110);     // [i*3+j]
    for (int i = 0; i < 3; ++i) K.c330[i] = (float)(w110[i * 3 + i]);
    double w111[27]; cgh::wigner3j(1, 1, 1, w111);     // [(i*3+j)*3+k]
    K.c4[0] = (float)(w111[(1 * 3 + 2) * 3 + 0] * s3);
    K.c4[1] = (float)(w111[(2 * 3 + 1) * 3 + 0] * s3);
    K.c4[2] = (float)(w111[(0 * 3 + 2) * 3 + 1] * s3);
    K.c4[3] = (float)(w111[(2 * 3 + 0) * 3 + 1] * s3);
    K.c4[4] = (float)(w111[(0 * 3 + 1) * 3 + 2] * s3);
    K.c4[5] = (float)(w111[(1 * 3 + 0) * 3 + 2] * s3);
    double w112[45]; cgh::wigner3j(1, 1, 2, w112);     // [(i*3+j)*5+k]
    K.c5[0]  = (float)(w112[(0 * 3 + 2) * 5 + 0] * s5);
    K.c5[1]  = (float)(w112[(2 * 3 + 0) * 5 + 0] * s5);
    K.c5[2]  = (float)(w112[(0 * 3 + 1) * 5 + 1] * s5);
    K.c5[3]  = (float)(w112[(1 * 3 + 0) * 5 + 1] * s5);
    K.c5[4]  = (float)(w112[(0 * 3 + 0) * 5 + 2] * s5);
    K.c5[5]  = (float)(w112[(1 * 3 + 1) * 5 + 2] * s5);
    K.c5[6]  = (float)(w112[(2 * 3 + 2) * 5 + 2] * s5);
    K.c5[7]  = (float)(w112[(1 * 3 + 2) * 5 + 3] * s5);
    K.c5[8]  = (float)(w112[(2 * 3 + 1) * 5 + 3] * s5);
    K.c5[9]  = (float)(w112[(0 * 3 + 0) * 5 + 4] * s5);
    K.c5[10] = (float)(w112[(2 * 3 + 2) * 5 + 4] * s5);
    return K;
}

// ---------------------------------------------------------------------------
// Kernel. The reference's raw reshapes mean: output row r <-> fixed (u,v) =
// (r>>5, r&31); within a row the layout is [seg][q*d3 + k], q in [0,2048).
// Row segment bases (after stable Irrep sort): 0e:0, 0e:2048, 1o:4096,
// 1o:10240, 1e:16384, 2e:22528; row width 32768.
// Input gathers follow the raw-reshape map: flat-slice pos p -> element
// in1[off + p + (p/W)*(rowW - W)].
// ---------------------------------------------------------------------------
__global__ __launch_bounds__(256, 8)
void ftp_kernel(const float* __restrict__ in1, const float* __restrict__ in2,
                float* __restrict__ out, Consts K)
{
    const int tid = threadIdx.x;
    const int row = blockIdx.x;
    const int u = row >> 5;
    const int v = row & 31;
    float* __restrict__ orow = out + (size_t)row * 32768;

    __shared__ __align__(16) float stage[3584];

    #pragma unroll 1
    for (int tile = 0; tile < 8; ++tile) {
        const int q0 = tile * 256;
        const int q  = q0 + tid;

        // --- gathers through the raw-reshape index map (all L2-resident) ---
        unsigned p;
        p = (unsigned)(u * 2048 + q);                         // in1 0e slice, W=64, rowW=256
        const float a0  = __ldg(in1 + p + (p >> 6) * 192);
        p = (unsigned)((0 * 64 + u) * 2048 + q);              // in1 1o slice, W=192, off=64
        const float a10 = __ldg(in1 + 64 + p + (p / 192u) * 64);
        p += 131072u;
        const float a11 = __ldg(in1 + 64 + p + (p / 192u) * 64);
        p += 131072u;
        const float a12 = __ldg(in1 + 64 + p + (p / 192u) * 64);
        p = (unsigned)(v * 2048 + q);                         // in2 0e slice, W=32, rowW=128
        const float b0  = __ldg(in2 + p + (p >> 5) * 96);
        p = (unsigned)((0 * 32 + v) * 2048 + q);              // in2 1o slice, W=96, off=32
        const float b10 = __ldg(in2 + 32 + p + (p / 96u) * 32);
        p += 65536u;
        const float b11 = __ldg(in2 + 32 + p + (p / 96u) * 32);
        p += 65536u;
        const float b12 = __ldg(in2 + 32 + p + (p / 96u) * 32);

        // --- 16 bilinear outputs per q (sparse CG structure) ---
        const float y0  = K.c000 * a0 * b0;
        const float y1  = K.c330[0] * a10 * b10 + K.c330[1] * a11 * b11 + K.c330[2] * a12 * b12;
        const float y20 = K.c2[0] * a0 * b10;
        const float y21 = K.c2[1] * a0 * b11;
        const float y22 = K.c2[2] * a0 * b12;
        const float y30 = K.c101[0] * a10 * b0;
        const float y31 = K.c101[1] * a11 * b0;
        const float y32 = K.c101[2] * a12 * b0;
        const float y40 = K.c4[0] * a11 * b12 + K.c4[1] * a12 * b11;
        const float y41 = K.c4[2] * a10 * b12 + K.c4[3] * a12 * b10;
        const float y42 = K.c4[4] * a10 * b11 + K.c4[5] * a11 * b10;
        const float y50 = K.c5[0] * a10 * b12 + K.c5[1]  * a12 * b10;
        const float y51 = K.c5[2] * a10 * b11 + K.c5[3]  * a11 * b10;
        const float y52 = K.c5[4] * a10 * b10 + K.c5[5]  * a11 * b11 + K.c5[6] * a12 * b12;
        const float y53 = K.c5[7] * a11 * b12 + K.c5[8]  * a12 * b11;
        const float y54 = K.c5[9] * a10 * b10 + K.c5[10] * a12 * b12;

        // scalar segments: already perfectly coalesced, streaming stores
        __stcs(orow + q,        y0);
        __stcs(orow + 2048 + q, y1);

        // k-interleaved segments: stage in SMEM, flush as coalesced STG.128
        stage[3 * tid + 0] = y20; stage[3 * tid + 1] = y21; stage[3 * tid + 2] = y22;
        stage[768  + 3 * tid + 0] = y30; stage[768  + 3 * tid + 1] = y31; stage[768  + 3 * tid + 2] = y32;
        stage[1536 + 3 * tid + 0] = y40; stage[1536 + 3 * tid + 1] = y41; stage[1536 + 3 * tid + 2] = y42;
        stage[2304 + 5 * tid + 0] = y50; stage[2304 + 5 * tid + 1] = y51;
        stage[2304 + 5 * tid + 2] = y52; stage[2304 + 5 * tid + 3] = y53;
        stage[2304 + 5 * tid + 4] = y54;
        __syncthreads();

        #pragma unroll
        for (int t0 = 0; t0 < 1024; t0 += 256) {
            const int t = t0 + tid;
            if (t < 896) {
                const float4 val = reinterpret_cast<const float4*>(stage)[t];
                int addr;
                if (t < 192)      addr = 4096  + q0 * 3 + 4 * t;          // 0e x 1o -> 1o
                else if (t < 384) addr = 10240 + q0 * 3 + 4 * t - 768;    // 1o x 0e -> 1o
                else if (t < 576) addr = 16384 + q0 * 3 + 4 * t - 1536;   // 1o x 1o -> 1e
                else              addr = 22528 + q0 * 5 + 4 * t - 2304;   // 1o x 1o -> 2e
                __stcs(reinterpret_cast<float4*>(orow + addr), val);
            }
        }
        __syncthreads();
    }
}

// ---------------------------------------------------------------------------
extern "C" void kernel_launch(void* const* d_in, const int* in_sizes, int n_in,
                              void* d_out, int out_size)
{
    (void)n_in; (void)out_size;
    Consts K = build_consts();   // pure host math, deterministic, runs at capture
    const float* in1 = (const float*)d_in[0];   // (2048, 256) fp32
    const float* in2 = (const float*)d_in[1];   // (2048, 128) fp32
    float* out = (float*)d_out;                 // (2048, 32768) fp32
    const int rows = in_sizes[0] / 256;         // 2048 output rows == (u,v) pairs
    ftp_kernel<<<rows, 256>>>(in1, in2, out, K);
}